// round 4
// baseline (speedup 1.0000x reference)
#include <cuda_runtime.h>
#include <cstdint>

// FSQCodebook: out[n] = sum_k (round(tanh(x[n,:]·W[k,:] + b[k]) * SCALE) + 1) * 3^k
// x: (65536, 1280) f32, W: (8, 1280) f32, b: (8) f32, out: 65536 (stored as f32)

#define NDIM_ 8
#define KDIM_ 1280
#define ROWS_PER_WARP 4
#define THREADS_ 256
#define WARPS_ (THREADS_ / 32)
#define ROWS_PER_BLOCK (ROWS_PER_WARP * WARPS_)   // 32
#define NROWS_ 65536
#define SCALE_F 0.9990000128746033f

__global__ __launch_bounds__(THREADS_, 2)
void fsq_kernel(const float* __restrict__ x,
                const float* __restrict__ W,
                const float* __restrict__ b,
                float* __restrict__ out) {
    __shared__ __align__(16) float Wsm[NDIM_ * KDIM_];   // 40 KB
    __shared__ float bsm[NDIM_];

    const int tid = threadIdx.x;

    // Stage W into shared memory (coalesced float4 copy: 2560 float4s / 256 thr)
    {
        const float4* Wg = reinterpret_cast<const float4*>(W);
        float4* Ws = reinterpret_cast<float4*>(Wsm);
        #pragma unroll
        for (int i = 0; i < (NDIM_ * KDIM_ / 4) / THREADS_; ++i)
            Ws[i * THREADS_ + tid] = Wg[i * THREADS_ + tid];
    }
    if (tid < NDIM_) bsm[tid] = b[tid];
    __syncthreads();

    const int warp = tid >> 5;
    const int lane = tid & 31;
    const int row0 = blockIdx.x * ROWS_PER_BLOCK + warp * ROWS_PER_WARP;
    const float* xrow = x + (size_t)row0 * KDIM_;

    // Scalar fp32 accumulators: [row][dim]
    float acc[ROWS_PER_WARP][NDIM_];
    #pragma unroll
    for (int r = 0; r < ROWS_PER_WARP; ++r)
        #pragma unroll
        for (int k = 0; k < NDIM_; ++k)
            acc[r][k] = 0.0f;

    // Main loop: lane covers columns (i*128 + lane*4 .. +3), 10 iterations.
    // x: coalesced LDG.128 per row; W: conflict-free LDS.128 reused across 4 rows.
    #pragma unroll 2
    for (int i = 0; i < KDIM_ / 128; ++i) {
        const int c = i * 128 + lane * 4;

        float4 xv[ROWS_PER_WARP];
        #pragma unroll
        for (int r = 0; r < ROWS_PER_WARP; ++r)
            xv[r] = *reinterpret_cast<const float4*>(xrow + r * KDIM_ + c);

        #pragma unroll
        for (int k = 0; k < NDIM_; ++k) {
            const float4 wv = *reinterpret_cast<const float4*>(Wsm + k * KDIM_ + c);
            #pragma unroll
            for (int r = 0; r < ROWS_PER_WARP; ++r) {
                acc[r][k] = fmaf(xv[r].x, wv.x, acc[r][k]);
                acc[r][k] = fmaf(xv[r].y, wv.y, acc[r][k]);
                acc[r][k] = fmaf(xv[r].z, wv.z, acc[r][k]);
                acc[r][k] = fmaf(xv[r].w, wv.w, acc[r][k]);
            }
        }
    }

    // Reduce across the warp; lane r (< ROWS_PER_WARP) keeps row r's result.
    float h[NDIM_];
    #pragma unroll
    for (int k = 0; k < NDIM_; ++k) h[k] = 0.0f;

    #pragma unroll
    for (int r = 0; r < ROWS_PER_WARP; ++r) {
        #pragma unroll
        for (int k = 0; k < NDIM_; ++k) {
            float s = acc[r][k];
            #pragma unroll
            for (int off = 16; off > 0; off >>= 1)
                s += __shfl_xor_sync(0xffffffffu, s, off);
            if (lane == r) h[k] = s + bsm[k];
        }
    }

    // Epilogue: only lanes 0..3 hold valid h; all lanes execute (SIMT), 4 write.
    float mu = 0.0f, p = 1.0f;
    #pragma unroll
    for (int k = 0; k < NDIM_; ++k) {
        float t = tanhf(h[k]) * SCALE_F;
        float q = rintf(t) + 1.0f;     // ternary {0,1,2}, round-half-even
        mu = fmaf(q, p, mu);
        p *= 3.0f;
    }
    if (lane < ROWS_PER_WARP)
        out[row0 + lane] = mu;         // store as float: 0..6560 exact in fp32
}

extern "C" void kernel_launch(void* const* d_in, const int* in_sizes, int n_in,
                              void* d_out, int out_size) {
    // Bind inputs by element count (robust to metadata ordering):
    //   x: 65536*1280 = 83886080, W: 8*1280 = 10240, b: 8
    const float* x = nullptr;
    const float* W = nullptr;
    const float* b = nullptr;
    for (int i = 0; i < n_in; ++i) {
        if (in_sizes[i] == NROWS_ * KDIM_)      x = (const float*)d_in[i];
        else if (in_sizes[i] == NDIM_ * KDIM_)  W = (const float*)d_in[i];
        else if (in_sizes[i] == NDIM_)          b = (const float*)d_in[i];
    }
    float* out = (float*)d_out;
    (void)out_size;

    const int blocks = NROWS_ / ROWS_PER_BLOCK;   // 2048
    fsq_kernel<<<blocks, THREADS_>>>(x, W, b, out);
}

// round 6
// speedup vs baseline: 1.0296x; 1.0296x over previous
#include <cuda_runtime.h>
#include <cstdint>

// FSQCodebook: out[n] = sum_k (round(tanh(x[n,:]·W[k,:] + b[k]) * SCALE) + 1) * 3^k
// x: (65536, 1280) f32, W: (8, 1280) f32, b: (8) f32, out: 65536 (stored as f32)

#define NDIM_ 8
#define KDIM_ 1280
#define ROWS_PER_WARP 4
#define THREADS_ 256
#define WARPS_ (THREADS_ / 32)
#define ROWS_PER_BLOCK (ROWS_PER_WARP * WARPS_)   // 32
#define NROWS_ 65536
#define SCALE_F 0.9990000128746033f

__device__ __forceinline__ void ffma2(unsigned long long& d,
                                      unsigned long long a,
                                      unsigned long long b) {
    asm volatile("fma.rn.f32x2 %0, %1, %2, %0;" : "+l"(d) : "l"(a), "l"(b));
}

__device__ __forceinline__ float pairsum(unsigned long long v) {
    float lo, hi;
    asm("mov.b64 {%0, %1}, %2;" : "=f"(lo), "=f"(hi) : "l"(v));
    return lo + hi;
}

__global__ __launch_bounds__(THREADS_, 2)
void fsq_kernel(const float* __restrict__ x,
                const float* __restrict__ W,
                const float* __restrict__ b,
                float* __restrict__ out) {
    __shared__ __align__(16) float Wsm[NDIM_ * KDIM_];   // 40 KB
    __shared__ float bsm[NDIM_];

    const int tid = threadIdx.x;

    // Stage W into shared memory (coalesced float4 copy: 2560 float4s / 256 thr)
    {
        const float4* Wg = reinterpret_cast<const float4*>(W);
        float4* Ws = reinterpret_cast<float4*>(Wsm);
        #pragma unroll
        for (int i = 0; i < (NDIM_ * KDIM_ / 4) / THREADS_; ++i)
            Ws[i * THREADS_ + tid] = Wg[i * THREADS_ + tid];
    }
    if (tid < NDIM_) bsm[tid] = b[tid];
    __syncthreads();

    const int warp = tid >> 5;
    const int lane = tid & 31;
    const int row0 = blockIdx.x * ROWS_PER_BLOCK + warp * ROWS_PER_WARP;
    const float* xrow = x + (size_t)row0 * KDIM_;

    // Packed f32x2 accumulators: [row][dim] — each holds a pair of partial sums.
    unsigned long long acc[ROWS_PER_WARP][NDIM_];
    #pragma unroll
    for (int r = 0; r < ROWS_PER_WARP; ++r)
        #pragma unroll
        for (int k = 0; k < NDIM_; ++k)
            acc[r][k] = 0ull;

    // Main loop: lane covers columns (i*128 + lane*4 .. +3), 10 iterations.
    // x: coalesced LDG.128 per row; W: conflict-free LDS.128 reused across 4 rows.
    // 64 packed FMAs per iteration (vs 128 scalar) — halves FMA issue pressure.
    #pragma unroll 2
    for (int i = 0; i < KDIM_ / 128; ++i) {
        const int c = i * 128 + lane * 4;

        ulonglong2 xv[ROWS_PER_WARP];
        #pragma unroll
        for (int r = 0; r < ROWS_PER_WARP; ++r)
            xv[r] = *reinterpret_cast<const ulonglong2*>(xrow + r * KDIM_ + c);

        #pragma unroll
        for (int k = 0; k < NDIM_; ++k) {
            const ulonglong2 wv =
                *reinterpret_cast<const ulonglong2*>(Wsm + k * KDIM_ + c);
            #pragma unroll
            for (int r = 0; r < ROWS_PER_WARP; ++r) {
                ffma2(acc[r][k], xv[r].x, wv.x);
                ffma2(acc[r][k], xv[r].y, wv.y);
            }
        }
    }

    // Reduce across the warp; lane r (< ROWS_PER_WARP) keeps row r's result.
    float h[NDIM_];
    #pragma unroll
    for (int k = 0; k < NDIM_; ++k) h[k] = 0.0f;

    #pragma unroll
    for (int r = 0; r < ROWS_PER_WARP; ++r) {
        #pragma unroll
        for (int k = 0; k < NDIM_; ++k) {
            float s = pairsum(acc[r][k]);
            #pragma unroll
            for (int off = 16; off > 0; off >>= 1)
                s += __shfl_xor_sync(0xffffffffu, s, off);
            if (lane == r) h[k] = s + bsm[k];
        }
    }

    // Epilogue: only lanes 0..3 hold valid h; all lanes execute (SIMT), 4 write.
    float mu = 0.0f, p = 1.0f;
    #pragma unroll
    for (int k = 0; k < NDIM_; ++k) {
        float t = tanhf(h[k]) * SCALE_F;
        float q = rintf(t) + 1.0f;     // ternary {0,1,2}, round-half-even
        mu = fmaf(q, p, mu);
        p *= 3.0f;
    }
    if (lane < ROWS_PER_WARP)
        out[row0 + lane] = mu;         // store as float: 0..6560 exact in fp32
}

extern "C" void kernel_launch(void* const* d_in, const int* in_sizes, int n_in,
                              void* d_out, int out_size) {
    // Bind inputs by element count (robust to metadata ordering):
    //   x: 65536*1280 = 83886080, W: 8*1280 = 10240, b: 8
    const float* x = nullptr;
    const float* W = nullptr;
    const float* b = nullptr;
    for (int i = 0; i < n_in; ++i) {
        if (in_sizes[i] == NROWS_ * KDIM_)      x = (const float*)d_in[i];
        else if (in_sizes[i] == NDIM_ * KDIM_)  W = (const float*)d_in[i];
        else if (in_sizes[i] == NDIM_)          b = (const float*)d_in[i];
    }
    float* out = (float*)d_out;
    (void)out_size;

    const int blocks = NROWS_ / ROWS_PER_BLOCK;   // 2048
    fsq_kernel<<<blocks, THREADS_>>>(x, W, b, out);
}